// round 16
// baseline (speedup 1.0000x reference)
#include <cuda_runtime.h>
#include <cuda_fp16.h>
#include <math.h>
#include <stdint.h>

#define NNODE   512
#define NGRAPH  8
#define E_DIM   1024
#define NHEADS  16
#define HD      64
#define NB      (NGRAPH*NHEADS)     // 128 heads
#define NROWS   (NNODE*NGRAPH)      // 4096
#define SCALING 0.125f              // 64^-0.5

// Scratch (device globals: allocation-free rule)
__device__ __half g_Xh [NROWS*E_DIM];      // query, fp16
__device__ __half g_Wih[3*E_DIM*E_DIM];    // in_w, fp16
__device__ __half g_Woh[E_DIM*E_DIM];      // out_w, fp16
__device__ __half g_Qh [NB*NNODE*HD];      // scaled Q, fp16
__device__ __half g_Kh [NB*NNODE*HD];
__device__ __half g_Vh [NB*NNODE*HD];
__device__ __half g_AOh[NROWS*E_DIM];      // attention out, fp16
__device__ float  g_P0 [NROWS*E_DIM];      // out-proj k-half-0 partials, fp32

// Cross-phase progress counters (zeroed by cvt_kernel each launch)
__device__ int g_cnt_qkv[8];      // per head-pair group: 3 cols x 32 bm = 96
__device__ int g_cnt_attnH[16];   // [rb][gp-half]: 64 head-CTAs each
__device__ int g_outflag[256];    // per out tile (bm*8+bn): khalf0 partial done

// ---------------------------------------------------------------------------
// Helpers
// ---------------------------------------------------------------------------
__device__ __forceinline__ unsigned smem_u32(const void* p){
    return (unsigned)__cvta_generic_to_shared(p);
}
__device__ __forceinline__ void cp16(unsigned dst, const void* src){
    asm volatile("cp.async.cg.shared.global [%0], [%1], 16;\n" :: "r"(dst), "l"(src));
}
__device__ __forceinline__ void cp_commit(){ asm volatile("cp.async.commit_group;\n" ::: "memory"); }
template<int N> __device__ __forceinline__ void cp_wait(){
    asm volatile("cp.async.wait_group %0;\n" :: "n"(N) : "memory");
}
__device__ __forceinline__ float fast_tanh(float x){
    float e = __expf(2.f*x);
    return 1.f - __fdividef(2.f, e + 1.f);
}
__device__ __forceinline__ void mma_f16(float c[4], const unsigned a[4], const unsigned b[2]){
    asm volatile(
        "mma.sync.aligned.m16n8k16.row.col.f32.f16.f16.f32 "
        "{%0,%1,%2,%3}, {%4,%5,%6,%7}, {%8,%9}, {%0,%1,%2,%3};"
        : "+f"(c[0]), "+f"(c[1]), "+f"(c[2]), "+f"(c[3])
        : "r"(a[0]), "r"(a[1]), "r"(a[2]), "r"(a[3]), "r"(b[0]), "r"(b[1]));
}
__device__ __forceinline__ void ldm_x4(unsigned* r, uint32_t a){
    asm volatile("ldmatrix.sync.aligned.m8n8.x4.shared.b16 {%0,%1,%2,%3}, [%4];"
        : "=r"(r[0]), "=r"(r[1]), "=r"(r[2]), "=r"(r[3]) : "r"(a));
}
__device__ __forceinline__ void ldm_x4_t(unsigned* r, uint32_t a){
    asm volatile("ldmatrix.sync.aligned.m8n8.x4.trans.shared.b16 {%0,%1,%2,%3}, [%4];"
        : "=r"(r[0]), "=r"(r[1]), "=r"(r[2]), "=r"(r[3]) : "r"(a));
}
__device__ __forceinline__ unsigned pack_h2(float a, float b){
    __half2 h = __floats2half2_rn(a, b);
    return *(unsigned*)&h;
}

// ---------------------------------------------------------------------------
// fp32 -> fp16 convert pre-pass (query, in_w, out_w) + counter reset
// ---------------------------------------------------------------------------
#define NQ4 (NROWS*E_DIM/4)        // 1048576
#define NI4 (3*E_DIM*E_DIM/4)      // 786432
#define NO4 (E_DIM*E_DIM/4)        // 262144
#define CVT_GRID ((NQ4+NI4+NO4)/256)

__global__ __launch_bounds__(256)
void cvt_kernel(const float4* __restrict__ q, const float4* __restrict__ iw,
                const float4* __restrict__ ow)
{
    if (blockIdx.x == 0) {
        int t = threadIdx.x;
        if (t < 8)  g_cnt_qkv[t] = 0;
        if (t < 16) g_cnt_attnH[t] = 0;
        g_outflag[t] = 0;                       // 256 threads, 256 flags
    }
    int i = blockIdx.x*256 + threadIdx.x;
    float4 v; __half2* dst;
    if (i < NQ4)            { v = q[i];          dst = (__half2*)g_Xh  + 2*(size_t)i; }
    else if (i < NQ4+NI4)   { int j = i-NQ4;     v = iw[j]; dst = (__half2*)g_Wih + 2*(size_t)j; }
    else                    { int j = i-NQ4-NI4; v = ow[j]; dst = (__half2*)g_Woh + 2*(size_t)j; }
    dst[0] = __floats2half2_rn(v.x, v.y);
    dst[1] = __floats2half2_rn(v.z, v.w);
}

// ---------------------------------------------------------------------------
// fp16 GEMM body: BM=128 BN=128 BK=32 halves, 4 warps (2x2), warp tile 64x64,
// 3-stage cp.async, stride 40 halves.
// MODE 0: qkv (K=1024), epilogue scatters fp16 Q/K/V.
// MODE 1: out k-half 0 (K=512, cols [0,512)), writes fp32 partial to g_P0,
//         sets per-tile flag.
// MODE 2: out k-half 1 (K=512, cols [512,1024)), waits per-tile flag at
//         epilogue, adds g_P0 + bias, writes final fp32 out.
// ---------------------------------------------------------------------------
#define H_ST  40
#define HA_BYTES (128*H_ST*2)       // 10240
#define HSTAGE  (2*HA_BYTES)        // 20480
#define HGEMM_SMEM (3*HSTAGE)       // 61440

template<int MODE>
__device__ __forceinline__ void gemm_body(char* smemc, int bm0, int bn0,
                                          const float* __restrict__ bias,
                                          float* __restrict__ Cout)
{
    const uint32_t sb = smem_u32(smemc);
    const __half* Ah = (MODE == 0) ? (const __half*)g_Xh  : (const __half*)g_AOh;
    const __half* Wh = (MODE == 0) ? (const __half*)g_Wih : (const __half*)g_Woh;
    const int koff = (MODE == 2) ? 512 : 0;
    const int NT   = (MODE == 0) ? 32 : 16;     // k-tiles

    const int tid = threadIdx.x;
    const int wid = tid >> 5, lane = tid & 31;
    const int wm  = wid >> 1, wn = wid & 1;     // 2x2 warp grid
    const int g   = lane >> 2, tg = lane & 3;

    float acc[4][8][4];
    #pragma unroll
    for (int i=0;i<4;i++)
        #pragma unroll
        for (int j=0;j<8;j++)
            #pragma unroll
            for (int k=0;k<4;k++) acc[i][j][k]=0.f;

    const __half* Ag0 = Ah + (size_t)bm0 * E_DIM + koff;
    const __half* Bg0 = Wh + (size_t)bn0 * E_DIM + koff;

    #define HLOAD(t) do { \
        uint32_t s_ = sb + ((t)%3)*HSTAGE; \
        const __half* Ag = Ag0 + (t)*32; \
        const __half* Bg = Bg0 + (t)*32; \
        _Pragma("unroll") \
        for (int j = 0; j < 4; j++) { \
            int ci = tid + 128*j; \
            int row = ci >> 2, cc = ci & 3; \
            cp16(s_ + row*80 + cc*16, Ag + (size_t)row*E_DIM + cc*8); \
            cp16(s_ + HA_BYTES + row*80 + cc*16, Bg + (size_t)row*E_DIM + cc*8); \
        } \
        cp_commit(); \
    } while (0)

    HLOAD(0); HLOAD(1);
    for (int t = 0; t < NT; t++) {
        if (t + 1 < NT) cp_wait<1>(); else cp_wait<0>();
        __syncthreads();
        if (t + 2 < NT) HLOAD(t+2);

        uint32_t as_ = sb + (t%3)*HSTAGE;
        uint32_t bs_ = as_ + HA_BYTES;
        #pragma unroll
        for (int ks = 0; ks < 32; ks += 16) {
            unsigned a[4][4];
            #pragma unroll
            for (int mt = 0; mt < 4; mt++)
                ldm_x4(a[mt], as_ + (wm*64 + mt*16 + (lane&15))*80
                              + (ks + ((lane>>4)<<3))*2);
            #pragma unroll
            for (int np = 0; np < 4; np++) {
                unsigned r[4];
                ldm_x4(r, bs_ + (wn*64 + np*16 + ((lane>>4)<<3) + (lane&7))*80
                          + (ks + (((lane>>3)&1)<<3))*2);
                unsigned b0[2] = {r[0], r[1]}, b1[2] = {r[2], r[3]};
                #pragma unroll
                for (int mt = 0; mt < 4; mt++) {
                    mma_f16(acc[mt][2*np],   a[mt], b0);
                    mma_f16(acc[mt][2*np+1], a[mt], b1);
                }
            }
        }
    }
    #undef HLOAD

    if (MODE == 0) {
        #pragma unroll
        for (int mt = 0; mt < 4; mt++)
            #pragma unroll
            for (int nt = 0; nt < 8; nt++)
                #pragma unroll
                for (int ii = 0; ii < 2; ii++) {
                    int r = bm0 + wm*64 + mt*16 + g + ii*8;
                    int c = bn0 + wn*64 + nt*8 + 2*tg;
                    float2 bv = *(const float2*)(bias + c);
                    float v0 = acc[mt][nt][ii*2]   + bv.x;
                    float v1 = acc[mt][nt][ii*2+1] + bv.y;
                    int which = c >> 10;
                    int e = c & 1023, h = e >> 6, d = e & 63;
                    int n = r >> 3, gg = r & 7;
                    int idx = ((gg*NHEADS + h)*NNODE + n)*HD + d;
                    if (which == 0)
                        *(__half2*)&g_Qh[idx] = __floats2half2_rn(v0*SCALING, v1*SCALING);
                    else if (which == 1)
                        *(__half2*)&g_Kh[idx] = __floats2half2_rn(v0, v1);
                    else
                        *(__half2*)&g_Vh[idx] = __floats2half2_rn(v0, v1);
                }
    } else if (MODE == 1) {
        #pragma unroll
        for (int mt = 0; mt < 4; mt++)
            #pragma unroll
            for (int nt = 0; nt < 8; nt++)
                #pragma unroll
                for (int ii = 0; ii < 2; ii++) {
                    int r = bm0 + wm*64 + mt*16 + g + ii*8;
                    int c = bn0 + wn*64 + nt*8 + 2*tg;
                    *(float2*)&g_P0[(size_t)r*E_DIM + c] =
                        make_float2(acc[mt][nt][ii*2], acc[mt][nt][ii*2+1]);
                }
        __threadfence();
        __syncthreads();
        if (tid == 0)
            atomicExch(&g_outflag[(bm0 >> 7)*8 + (bn0 >> 7)], 1);
    } else {
        // wait for khalf0 partial of this tile (mainloop already done)
        if (tid == 0) {
            while (atomicAdd(&g_outflag[(bm0 >> 7)*8 + (bn0 >> 7)], 0) == 0)
                __nanosleep(128);
        }
        __syncthreads();
        __threadfence();
        #pragma unroll
        for (int mt = 0; mt < 4; mt++)
            #pragma unroll
            for (int nt = 0; nt < 8; nt++)
                #pragma unroll
                for (int ii = 0; ii < 2; ii++) {
                    int r = bm0 + wm*64 + mt*16 + g + ii*8;
                    int c = bn0 + wn*64 + nt*8 + 2*tg;
                    float2 bv = *(const float2*)(bias + c);
                    float2 p0 = *(const float2*)&g_P0[(size_t)r*E_DIM + c];
                    float2 val = make_float2(acc[mt][nt][ii*2]   + p0.x + bv.x,
                                             acc[mt][nt][ii*2+1] + p0.y + bv.y);
                    *(float2*)&Cout[(size_t)r*E_DIM + c] = val;
                }
    }
}

// ---------------------------------------------------------------------------
// Flash attention body, single-pass softmax (R14 — measured best).
// ---------------------------------------------------------------------------
#define AT_ST 72     // halves per row (64 + 8 pad) = 144 B
#define SB_ST 72     // floats per staged row (64 + 8 pad) = 288 B
#define ATTN_SMEM (5*64*AT_ST*2 + 2*64*SB_ST*4)   // 82944

__device__ __forceinline__ void at_load64(__half* dst, const __half* src, int tid)
{
    #pragma unroll
    for (int j = 0; j < 4; j++) {
        int ci = tid + 128*j;                 // 512 chunks of 16B
        int row = ci >> 3, cc = ci & 7;
        cp16(smem_u32(dst + row*AT_ST) + cc*16, src + (size_t)row*HD + cc*8);
    }
}

__device__ __forceinline__ void stage_load(float* dstB, float* dstG,
                                           const float* bsrc, const float* gsrc,
                                           int lane)
{
    #pragma unroll
    for (int j = 0; j < 8; j++) {
        int idx = lane + 32*j;               // 256 chunks over 16 rows x 16
        int row = idx >> 4, c16 = idx & 15;
        cp16(smem_u32(dstB + row*SB_ST + c16*4), bsrc + (size_t)row*NNODE + c16*4);
        cp16(smem_u32(dstG + row*SB_ST + c16*4), gsrc + (size_t)row*NNODE + c16*4);
    }
}

__device__ __forceinline__ void attn_body(__half* ash, int b, int rb,
                                          const float* __restrict__ bias,
                                          const float* __restrict__ gaw)
{
    __half* Qs = ash;
    __half* K0 = ash + 1*64*AT_ST;
    __half* K1 = ash + 2*64*AT_ST;
    __half* V0 = ash + 3*64*AT_ST;
    __half* V1 = ash + 4*64*AT_ST;
    float* stageB = (float*)(ash + 5*64*AT_ST);
    float* stageG = stageB + 64*SB_ST;

    const int tid = threadIdx.x;
    const int wid = tid >> 5, lane = tid & 31;
    const int g   = lane >> 2, tg = lane & 3;

    const __half* Kg = g_Kh + (size_t)b*NNODE*HD;
    const __half* Vg = g_Vh + (size_t)b*NNODE*HD;

    float* myB = stageB + wid*16*SB_ST;
    float* myG = stageG + wid*16*SB_ST;
    const float* bwarp = bias + ((size_t)b*NNODE + rb*64 + wid*16)*NNODE;
    const float* gwarp = gaw  + ((size_t)b*NNODE + rb*64 + wid*16)*NNODE;

    at_load64(Qs, g_Qh + ((size_t)b*NNODE + rb*64)*HD, tid);
    at_load64(K0, Kg, tid);
    at_load64(V0, Vg, tid);
    stage_load(myB, myG, bwarp, gwarp, lane);
    cp_commit();

    float l0 = 0.f, l1 = 0.f;
    float o[8][4];
    #pragma unroll
    for (int j=0;j<8;j++)
        #pragma unroll
        for (int k=0;k<4;k++) o[j][k]=0.f;
    unsigned qf[4][4];

    const uint32_t qs_ = smem_u32(Qs);
    const uint32_t kb_[2] = { smem_u32(K0), smem_u32(K1) };
    const uint32_t vb_[2] = { smem_u32(V0), smem_u32(V1) };
    const float* sB = myB + g*SB_ST + 2*tg;
    const float* sG = myG + g*SB_ST + 2*tg;

    for (int c = 0; c < 8; c++) {
        cp_wait<0>();
        __syncthreads();

        if (c == 0) {
            #pragma unroll
            for (int t = 0; t < 4; t++)
                ldm_x4(qf[t], qs_ + (wid*16 + (lane&15))*144
                              + (t*16 + ((lane>>4)<<3))*2);
        }

        float2 breg[8][2], greg[8][2];
        #pragma unroll
        for (int j = 0; j < 8; j++)
            #pragma unroll
            for (int h = 0; h < 2; h++) {
                breg[j][h] = *(const float2*)(sB + h*8*SB_ST + j*8);
                greg[j][h] = *(const float2*)(sG + h*8*SB_ST + j*8);
            }

        if (c + 1 < 8) {
            at_load64(c & 1 ? K0 : K1, Kg + (size_t)(c+1)*64*HD, tid);
            at_load64(c & 1 ? V0 : V1, Vg + (size_t)(c+1)*64*HD, tid);
            stage_load(myB, myG, bwarp + (c+1)*64, gwarp + (c+1)*64, lane);
            cp_commit();
        }

        // ---- QK ----
        float s[8][4];
        #pragma unroll
        for (int j=0;j<8;j++)
            #pragma unroll
            for (int k=0;k<4;k++) s[j][k]=0.f;

        const uint32_t kbase = kb_[c & 1];
        #pragma unroll
        for (int t = 0; t < 4; t++) {
            #pragma unroll
            for (int np = 0; np < 4; np++) {
                unsigned r[4];
                ldm_x4(r, kbase + (np*16 + ((lane>>4)<<3) + (lane&7))*144
                          + (t*16 + (((lane>>3)&1)<<3))*2);
                unsigned b0[2] = {r[0], r[1]}, b1[2] = {r[2], r[3]};
                mma_f16(s[2*np],   qf[t], b0);
                mma_f16(s[2*np+1], qf[t], b1);
            }
        }

        // ---- single-pass: p = exp(s + bias); accumulate row sums ----
        float sum0 = 0.f, sum1 = 0.f;
        #pragma unroll
        for (int j = 0; j < 8; j++) {
            s[j][0] = __expf(s[j][0] + breg[j][0].x);
            s[j][1] = __expf(s[j][1] + breg[j][0].y);
            s[j][2] = __expf(s[j][2] + breg[j][1].x);
            s[j][3] = __expf(s[j][3] + breg[j][1].y);
            sum0 += s[j][0] + s[j][1];
            sum1 += s[j][2] + s[j][3];
        }
        l0 += sum0;
        l1 += sum1;

        // ---- P = p * tanh(gaw) ----
        #pragma unroll
        for (int j = 0; j < 8; j++) {
            s[j][0] *= fast_tanh(greg[j][0].x);
            s[j][1] *= fast_tanh(greg[j][0].y);
            s[j][2] *= fast_tanh(greg[j][1].x);
            s[j][3] *= fast_tanh(greg[j][1].y);
        }

        // pack P into PV A-fragments (no smem round-trip)
        unsigned pa[4][4];
        #pragma unroll
        for (int t = 0; t < 4; t++) {
            pa[t][0] = pack_h2(s[2*t][0],   s[2*t][1]);
            pa[t][1] = pack_h2(s[2*t][2],   s[2*t][3]);
            pa[t][2] = pack_h2(s[2*t+1][0], s[2*t+1][1]);
            pa[t][3] = pack_h2(s[2*t+1][2], s[2*t+1][3]);
        }

        // ---- PV: o[16x64] += P[16x64] * V[64x64] ----
        const uint32_t vbase = vb_[c & 1];
        #pragma unroll
        for (int t = 0; t < 4; t++) {
            #pragma unroll
            for (int jp = 0; jp < 4; jp++) {
                unsigned r[4];
                ldm_x4_t(r, vbase + (t*16 + (((lane>>3)&1)<<3) + (lane&7))*144
                            + (jp*16 + ((lane>>4)<<3))*2);
                unsigned b0[2] = {r[0], r[1]}, b1[2] = {r[2], r[3]};
                mma_f16(o[2*jp],   pa[t], b0);
                mma_f16(o[2*jp+1], pa[t], b1);
            }
        }
    }

    // row sums: quad-reduce once at the end
    l0 += __shfl_xor_sync(0xffffffffu, l0, 1);
    l0 += __shfl_xor_sync(0xffffffffu, l0, 2);
    l1 += __shfl_xor_sync(0xffffffffu, l1, 1);
    l1 += __shfl_xor_sync(0xffffffffu, l1, 2);

    const int gg = b >> 4, h = b & 15;
    const float inv0 = __fdividef(1.f, l0);
    const float inv1 = __fdividef(1.f, l1);
    const int n0 = rb*64 + wid*16 + g;
    #pragma unroll
    for (int j = 0; j < 8; j++) {
        int d = j*8 + 2*tg;
        *(__half2*)&g_AOh[(size_t)(n0*NGRAPH + gg)*E_DIM + h*HD + d] =
            __floats2half2_rn(o[j][0]*inv0, o[j][1]*inv0);
        *(__half2*)&g_AOh[(size_t)((n0+8)*NGRAPH + gg)*E_DIM + h*HD + d] =
            __floats2half2_rn(o[j][2]*inv1, o[j][3]*inv1);
    }
}

// ---------------------------------------------------------------------------
// Mega-kernel:
//   [0,768):     QKV tiles, bm fastest, grp-major columns
//   [768,1792):  attention, gp-major (R14 best ordering); increments
//                g_cnt_attnH[rb][gp>>2]
//   [1792,2048): out-proj k-half 0 -> g_P0 (deps: gp0-3, ready long before
//                dispatch -> zero spin; overlaps attn drain wave)
//   [2048,2304): out-proj k-half 1 -> final (waits khalf0 flag at epilogue)
// ---------------------------------------------------------------------------
#define MEGA_SMEM ATTN_SMEM   // 82944 >= HGEMM_SMEM

__global__ __launch_bounds__(128, 2)
void mega_kernel(const float* __restrict__ in_b,
                 const float* __restrict__ attnbias,
                 const float* __restrict__ gaw,
                 const float* __restrict__ out_b,
                 float* __restrict__ out)
{
    extern __shared__ char smem[];
    const int cta = blockIdx.x;
    const int tid = threadIdx.x;

    if (cta < 768) {
        int bm  = cta & 31;
        int bnp = cta >> 5;                    // 0..23, grp-major
        int grp = bnp / 3, rem = bnp % 3;
        int L   = rem * 8 + grp;
        gemm_body<0>(smem, bm*128, L*128, in_b, nullptr);
        __threadfence();
        __syncthreads();
        if (tid == 0) atomicAdd(&g_cnt_qkv[grp], 1);
    } else if (cta < 1792) {
        int t  = cta - 768;
        int gp = t >> 7;                       // 0..7  (gp-major: best attn)
        int u  = t & 127;
        int rb = u >> 4;                       // 0..7
        int v  = u & 15;
        int gg = v >> 1, hh = v & 1;
        int b  = gg*NHEADS + gp*2 + hh;
        if (tid == 0) {
            while (atomicAdd(&g_cnt_qkv[gp], 0) < 96) __nanosleep(256);
        }
        __syncthreads();
        __threadfence();
        attn_body((__half*)smem, b, rb, attnbias, gaw);
        __threadfence();
        __syncthreads();
        if (tid == 0) atomicAdd(&g_cnt_attnH[rb*2 + (gp >> 2)], 1);
    } else if (cta < 2048) {
        // ---- out k-half 0 (heads 0-7 = gp0-3) ----
        int t  = cta - 1792;
        int bm = t & 31;
        int bn = t >> 5;
        if (tid == 0) {
            while (atomicAdd(&g_cnt_attnH[(bm >> 2)*2 + 0], 0) < 64) __nanosleep(256);
        }
        __syncthreads();
        __threadfence();
        gemm_body<1>(smem, bm*128, bn*128, out_b, out);
    } else {
        // ---- out k-half 1 (heads 8-15 = gp4-7), final write ----
        int t  = cta - 2048;
        int bm = t & 31;
        int bn = t >> 5;
        if (tid == 0) {
            while (atomicAdd(&g_cnt_attnH[(bm >> 2)*2 + 1], 0) < 64) __nanosleep(256);
        }
        __syncthreads();
        __threadfence();
        gemm_body<2>(smem, bm*128, bn*128, out_b, out);
    }
}

// ---------------------------------------------------------------------------
extern "C" void kernel_launch(void* const* d_in, const int* in_sizes, int n_in,
                              void* d_out, int out_size)
{
    const float* query    = (const float*)d_in[0];
    const float* attnbias = (const float*)d_in[1];
    const float* gaw      = (const float*)d_in[2];
    const float* in_w     = (const float*)d_in[3];
    const float* in_b     = (const float*)d_in[4];
    const float* out_w    = (const float*)d_in[5];
    const float* out_b    = (const float*)d_in[6];
    float* out = (float*)d_out;

    static int configured = 0;
    if (!configured) {
        cudaFuncSetAttribute(mega_kernel,
                             cudaFuncAttributeMaxDynamicSharedMemorySize, MEGA_SMEM);
        configured = 1;
    }

    cvt_kernel<<<CVT_GRID, 256>>>((const float4*)query, (const float4*)in_w,
                                  (const float4*)out_w);

    mega_kernel<<<2304, 128, MEGA_SMEM>>>(in_b, attnbias, gaw, out_b, out);
}

// round 17
// speedup vs baseline: 1.0853x; 1.0853x over previous
#include <cuda_runtime.h>
#include <cuda_fp16.h>
#include <math.h>
#include <stdint.h>

#define NNODE   512
#define NGRAPH  8
#define E_DIM   1024
#define NHEADS  16
#define HD      64
#define NB      (NGRAPH*NHEADS)     // 128 heads
#define NROWS   (NNODE*NGRAPH)      // 4096
#define SCALING 0.125f              // 64^-0.5

// Scratch (device globals: allocation-free rule)
__device__ __half g_Xh [NROWS*E_DIM];      // query, fp16
__device__ __half g_Wih[3*E_DIM*E_DIM];    // in_w, fp16
__device__ __half g_Woh[E_DIM*E_DIM];      // out_w, fp16
__device__ __half g_Qh [NB*NNODE*HD];      // scaled Q, fp16
__device__ __half g_Kh [NB*NNODE*HD];
__device__ __half g_Vh [NB*NNODE*HD];
__device__ __half g_AOh[NROWS*E_DIM];      // attention out, fp16

// Cross-phase progress counters (zeroed by cvt_kernel each launch)
__device__ int g_cnt_qkv[8];   // per head-pair group: 3 cols x 32 bm = 96
__device__ int g_cnt_attn[8];  // per rb: 128 head-CTAs

// ---------------------------------------------------------------------------
// Helpers
// ---------------------------------------------------------------------------
__device__ __forceinline__ unsigned smem_u32(const void* p){
    return (unsigned)__cvta_generic_to_shared(p);
}
__device__ __forceinline__ void cp16(unsigned dst, const void* src){
    asm volatile("cp.async.cg.shared.global [%0], [%1], 16;\n" :: "r"(dst), "l"(src));
}
__device__ __forceinline__ void cp_commit(){ asm volatile("cp.async.commit_group;\n" ::: "memory"); }
template<int N> __device__ __forceinline__ void cp_wait(){
    asm volatile("cp.async.wait_group %0;\n" :: "n"(N) : "memory");
}
__device__ __forceinline__ float fast_tanh(float x){
    float e = __expf(2.f*x);
    return 1.f - __fdividef(2.f, e + 1.f);
}
__device__ __forceinline__ void mma_f16(float c[4], const unsigned a[4], const unsigned b[2]){
    asm volatile(
        "mma.sync.aligned.m16n8k16.row.col.f32.f16.f16.f32 "
        "{%0,%1,%2,%3}, {%4,%5,%6,%7}, {%8,%9}, {%0,%1,%2,%3};"
        : "+f"(c[0]), "+f"(c[1]), "+f"(c[2]), "+f"(c[3])
        : "r"(a[0]), "r"(a[1]), "r"(a[2]), "r"(a[3]), "r"(b[0]), "r"(b[1]));
}
__device__ __forceinline__ void ldm_x4(unsigned* r, uint32_t a){
    asm volatile("ldmatrix.sync.aligned.m8n8.x4.shared.b16 {%0,%1,%2,%3}, [%4];"
        : "=r"(r[0]), "=r"(r[1]), "=r"(r[2]), "=r"(r[3]) : "r"(a));
}
__device__ __forceinline__ void ldm_x4_t(unsigned* r, uint32_t a){
    asm volatile("ldmatrix.sync.aligned.m8n8.x4.trans.shared.b16 {%0,%1,%2,%3}, [%4];"
        : "=r"(r[0]), "=r"(r[1]), "=r"(r[2]), "=r"(r[3]) : "r"(a));
}
__device__ __forceinline__ unsigned pack_h2(float a, float b){
    __half2 h = __floats2half2_rn(a, b);
    return *(unsigned*)&h;
}

// ---------------------------------------------------------------------------
// fp32 -> fp16 convert pre-pass (query, in_w, out_w) + counter reset
// ---------------------------------------------------------------------------
#define NQ4 (NROWS*E_DIM/4)        // 1048576
#define NI4 (3*E_DIM*E_DIM/4)      // 786432
#define NO4 (E_DIM*E_DIM/4)        // 262144
#define CVT_GRID ((NQ4+NI4+NO4)/256)

__global__ __launch_bounds__(256)
void cvt_kernel(const float4* __restrict__ q, const float4* __restrict__ iw,
                const float4* __restrict__ ow)
{
    if (blockIdx.x == 0 && threadIdx.x < 8) {
        g_cnt_qkv[threadIdx.x]  = 0;
        g_cnt_attn[threadIdx.x] = 0;
    }
    int i = blockIdx.x*256 + threadIdx.x;
    float4 v; __half2* dst;
    if (i < NQ4)            { v = q[i];          dst = (__half2*)g_Xh  + 2*(size_t)i; }
    else if (i < NQ4+NI4)   { int j = i-NQ4;     v = iw[j]; dst = (__half2*)g_Wih + 2*(size_t)j; }
    else                    { int j = i-NQ4-NI4; v = ow[j]; dst = (__half2*)g_Woh + 2*(size_t)j; }
    dst[0] = __floats2half2_rn(v.x, v.y);
    dst[1] = __floats2half2_rn(v.z, v.w);
}

// ---------------------------------------------------------------------------
// fp16 GEMM body (R5 measured-best config): BM=128 BN=128 BK=32 halves,
// 4 warps (2x2), warp tile 64x64, 3-stage cp.async, stride 40 halves.
// ---------------------------------------------------------------------------
#define H_ST  40
#define HA_BYTES (128*H_ST*2)       // 10240
#define HSTAGE  (2*HA_BYTES)        // 20480
#define HGEMM_SMEM (3*HSTAGE)       // 61440

template<bool QKV>
__device__ __forceinline__ void gemm_body(char* smemc, int bm0, int bn0,
                                          const float* __restrict__ bias,
                                          float* __restrict__ Cout)
{
    const uint32_t sb = smem_u32(smemc);
    const __half* Ah = QKV ? (const __half*)g_Xh  : (const __half*)g_AOh;
    const __half* Wh = QKV ? (const __half*)g_Wih : (const __half*)g_Woh;

    const int tid = threadIdx.x;
    const int wid = tid >> 5, lane = tid & 31;
    const int wm  = wid >> 1, wn = wid & 1;       // 2x2 warp grid
    const int g   = lane >> 2, tg = lane & 3;

    float acc[4][8][4];
    #pragma unroll
    for (int i=0;i<4;i++)
        #pragma unroll
        for (int j=0;j<8;j++)
            #pragma unroll
            for (int k=0;k<4;k++) acc[i][j][k]=0.f;

    const __half* Ag0 = Ah + (size_t)bm0 * E_DIM;
    const __half* Bg0 = Wh + (size_t)bn0 * E_DIM;

    #define HLOAD(t) do { \
        uint32_t s_ = sb + ((t)%3)*HSTAGE; \
        const __half* Ag = Ag0 + (t)*32; \
        const __half* Bg = Bg0 + (t)*32; \
        _Pragma("unroll") \
        for (int j = 0; j < 4; j++) { \
            int ci = tid + 128*j; \
            int row = ci >> 2, cc = ci & 3; \
            cp16(s_ + row*80 + cc*16, Ag + (size_t)row*E_DIM + cc*8); \
            cp16(s_ + HA_BYTES + row*80 + cc*16, Bg + (size_t)row*E_DIM + cc*8); \
        } \
        cp_commit(); \
    } while (0)

    HLOAD(0); HLOAD(1);
    for (int t = 0; t < 32; t++) {
        if (t + 1 < 32) cp_wait<1>(); else cp_wait<0>();
        __syncthreads();
        if (t + 2 < 32) HLOAD(t+2);

        uint32_t as_ = sb + (t%3)*HSTAGE;
        uint32_t bs_ = as_ + HA_BYTES;
        #pragma unroll
        for (int ks = 0; ks < 32; ks += 16) {
            unsigned a[4][4];
            #pragma unroll
            for (int mt = 0; mt < 4; mt++)
                ldm_x4(a[mt], as_ + (wm*64 + mt*16 + (lane&15))*80
                              + (ks + ((lane>>4)<<3))*2);
            #pragma unroll
            for (int np = 0; np < 4; np++) {
                unsigned r[4];
                ldm_x4(r, bs_ + (wn*64 + np*16 + ((lane>>4)<<3) + (lane&7))*80
                          + (ks + (((lane>>3)&1)<<3))*2);
                unsigned b0[2] = {r[0], r[1]}, b1[2] = {r[2], r[3]};
                #pragma unroll
                for (int mt = 0; mt < 4; mt++) {
                    mma_f16(acc[mt][2*np],   a[mt], b0);
                    mma_f16(acc[mt][2*np+1], a[mt], b1);
                }
            }
        }
    }
    #undef HLOAD

    if (QKV) {
        #pragma unroll
        for (int mt = 0; mt < 4; mt++)
            #pragma unroll
            for (int nt = 0; nt < 8; nt++)
                #pragma unroll
                for (int ii = 0; ii < 2; ii++) {
                    int r = bm0 + wm*64 + mt*16 + g + ii*8;
                    int c = bn0 + wn*64 + nt*8 + 2*tg;
                    float2 bv = *(const float2*)(bias + c);
                    float v0 = acc[mt][nt][ii*2]   + bv.x;
                    float v1 = acc[mt][nt][ii*2+1] + bv.y;
                    int which = c >> 10;
                    int e = c & 1023, h = e >> 6, d = e & 63;
                    int n = r >> 3, gg = r & 7;
                    int idx = ((gg*NHEADS + h)*NNODE + n)*HD + d;
                    if (which == 0)
                        *(__half2*)&g_Qh[idx] = __floats2half2_rn(v0*SCALING, v1*SCALING);
                    else if (which == 1)
                        *(__half2*)&g_Kh[idx] = __floats2half2_rn(v0, v1);
                    else
                        *(__half2*)&g_Vh[idx] = __floats2half2_rn(v0, v1);
                }
    } else {
        #pragma unroll
        for (int mt = 0; mt < 4; mt++)
            #pragma unroll
            for (int nt = 0; nt < 8; nt++)
                #pragma unroll
                for (int ii = 0; ii < 2; ii++) {
                    int r = bm0 + wm*64 + mt*16 + g + ii*8;
                    int c = bn0 + wn*64 + nt*8 + 2*tg;
                    float2 bv = *(const float2*)(bias + c);
                    float2 val = make_float2(acc[mt][nt][ii*2]   + bv.x,
                                             acc[mt][nt][ii*2+1] + bv.y);
                    *(float2*)&Cout[(size_t)r*E_DIM + c] = val;
                }
    }
}

// ---------------------------------------------------------------------------
// Flash attention body, single-pass softmax (R14 — measured best), with
// COALESCED OUTPUT: the epilogue stages each warp's 16x64 tile in its
// warp-private bias-stage smem (free after chunk 7) and writes g_AOh as
// full 128B lines instead of scattered 4B stores.
// ---------------------------------------------------------------------------
#define AT_ST 72     // halves per row (64 + 8 pad) = 144 B
#define SB_ST 72     // floats per staged row (64 + 8 pad) = 288 B
#define ATTN_SMEM (5*64*AT_ST*2 + 2*64*SB_ST*4)   // 82944

__device__ __forceinline__ void at_load64(__half* dst, const __half* src, int tid)
{
    #pragma unroll
    for (int j = 0; j < 4; j++) {
        int ci = tid + 128*j;                 // 512 chunks of 16B
        int row = ci >> 3, cc = ci & 7;
        cp16(smem_u32(dst + row*AT_ST) + cc*16, src + (size_t)row*HD + cc*8);
    }
}

__device__ __forceinline__ void stage_load(float* dstB, float* dstG,
                                           const float* bsrc, const float* gsrc,
                                           int lane)
{
    #pragma unroll
    for (int j = 0; j < 8; j++) {
        int idx = lane + 32*j;               // 256 chunks over 16 rows x 16
        int row = idx >> 4, c16 = idx & 15;
        cp16(smem_u32(dstB + row*SB_ST + c16*4), bsrc + (size_t)row*NNODE + c16*4);
        cp16(smem_u32(dstG + row*SB_ST + c16*4), gsrc + (size_t)row*NNODE + c16*4);
    }
}

__device__ __forceinline__ void attn_body(__half* ash, int b, int rb,
                                          const float* __restrict__ bias,
                                          const float* __restrict__ gaw)
{
    __half* Qs = ash;
    __half* K0 = ash + 1*64*AT_ST;
    __half* K1 = ash + 2*64*AT_ST;
    __half* V0 = ash + 3*64*AT_ST;
    __half* V1 = ash + 4*64*AT_ST;
    float* stageB = (float*)(ash + 5*64*AT_ST);
    float* stageG = stageB + 64*SB_ST;

    const int tid = threadIdx.x;
    const int wid = tid >> 5, lane = tid & 31;
    const int g   = lane >> 2, tg = lane & 3;

    const __half* Kg = g_Kh + (size_t)b*NNODE*HD;
    const __half* Vg = g_Vh + (size_t)b*NNODE*HD;

    float* myB = stageB + wid*16*SB_ST;
    float* myG = stageG + wid*16*SB_ST;
    const float* bwarp = bias + ((size_t)b*NNODE + rb*64 + wid*16)*NNODE;
    const float* gwarp = gaw  + ((size_t)b*NNODE + rb*64 + wid*16)*NNODE;

    at_load64(Qs, g_Qh + ((size_t)b*NNODE + rb*64)*HD, tid);
    at_load64(K0, Kg, tid);
    at_load64(V0, Vg, tid);
    stage_load(myB, myG, bwarp, gwarp, lane);
    cp_commit();

    float l0 = 0.f, l1 = 0.f;
    float o[8][4];
    #pragma unroll
    for (int j=0;j<8;j++)
        #pragma unroll
        for (int k=0;k<4;k++) o[j][k]=0.f;
    unsigned qf[4][4];

    const uint32_t qs_ = smem_u32(Qs);
    const uint32_t kb_[2] = { smem_u32(K0), smem_u32(K1) };
    const uint32_t vb_[2] = { smem_u32(V0), smem_u32(V1) };
    const float* sB = myB + g*SB_ST + 2*tg;
    const float* sG = myG + g*SB_ST + 2*tg;

    for (int c = 0; c < 8; c++) {
        cp_wait<0>();
        __syncthreads();

        if (c == 0) {
            #pragma unroll
            for (int t = 0; t < 4; t++)
                ldm_x4(qf[t], qs_ + (wid*16 + (lane&15))*144
                              + (t*16 + ((lane>>4)<<3))*2);
        }

        float2 breg[8][2], greg[8][2];
        #pragma unroll
        for (int j = 0; j < 8; j++)
            #pragma unroll
            for (int h = 0; h < 2; h++) {
                breg[j][h] = *(const float2*)(sB + h*8*SB_ST + j*8);
                greg[j][h] = *(const float2*)(sG + h*8*SB_ST + j*8);
            }

        if (c + 1 < 8) {
            at_load64(c & 1 ? K0 : K1, Kg + (size_t)(c+1)*64*HD, tid);
            at_load64(c & 1 ? V0 : V1, Vg + (size_t)(c+1)*64*HD, tid);
            stage_load(myB, myG, bwarp + (c+1)*64, gwarp + (c+1)*64, lane);
            cp_commit();
        }

        // ---- QK ----
        float s[8][4];
        #pragma unroll
        for (int j=0;j<8;j++)
            #pragma unroll
            for (int k=0;k<4;k++) s[j][k]=0.f;

        const uint32_t kbase = kb_[c & 1];
        #pragma unroll
        for (int t = 0; t < 4; t++) {
            #pragma unroll
            for (int np = 0; np < 4; np++) {
                unsigned r[4];
                ldm_x4(r, kbase + (np*16 + ((lane>>4)<<3) + (lane&7))*144
                          + (t*16 + (((lane>>3)&1)<<3))*2);
                unsigned b0[2] = {r[0], r[1]}, b1[2] = {r[2], r[3]};
                mma_f16(s[2*np],   qf[t], b0);
                mma_f16(s[2*np+1], qf[t], b1);
            }
        }

        // ---- single-pass: p = exp(s + bias); accumulate row sums ----
        float sum0 = 0.f, sum1 = 0.f;
        #pragma unroll
        for (int j = 0; j < 8; j++) {
            s[j][0] = __expf(s[j][0] + breg[j][0].x);
            s[j][1] = __expf(s[j][1] + breg[j][0].y);
            s[j][2] = __expf(s[j][2] + breg[j][1].x);
            s[j][3] = __expf(s[j][3] + breg[j][1].y);
            sum0 += s[j][0] + s[j][1];
            sum1 += s[j][2] + s[j][3];
        }
        l0 += sum0;
        l1 += sum1;

        // ---- P = p * tanh(gaw) ----
        #pragma unroll
        for (int j = 0; j < 8; j++) {
            s[j][0] *= fast_tanh(greg[j][0].x);
            s[j][1] *= fast_tanh(greg[j][0].y);
            s[j][2] *= fast_tanh(greg[j][1].x);
            s[j][3] *= fast_tanh(greg[j][1].y);
        }

        // pack P into PV A-fragments (no smem round-trip)
        unsigned pa[4][4];
        #pragma unroll
        for (int t = 0; t < 4; t++) {
            pa[t][0] = pack_h2(s[2*t][0],   s[2*t][1]);
            pa[t][1] = pack_h2(s[2*t][2],   s[2*t][3]);
            pa[t][2] = pack_h2(s[2*t+1][0], s[2*t+1][1]);
            pa[t][3] = pack_h2(s[2*t+1][2], s[2*t+1][3]);
        }

        // ---- PV: o[16x64] += P[16x64] * V[64x64] ----
        const uint32_t vbase = vb_[c & 1];
        #pragma unroll
        for (int t = 0; t < 4; t++) {
            #pragma unroll
            for (int jp = 0; jp < 4; jp++) {
                unsigned r[4];
                ldm_x4_t(r, vbase + (t*16 + (((lane>>3)&1)<<3) + (lane&7))*144
                            + (jp*16 + ((lane>>4)<<3))*2);
                unsigned b0[2] = {r[0], r[1]}, b1[2] = {r[2], r[3]};
                mma_f16(o[2*jp],   pa[t], b0);
                mma_f16(o[2*jp+1], pa[t], b1);
            }
        }
    }

    // row sums: quad-reduce once at the end
    l0 += __shfl_xor_sync(0xffffffffu, l0, 1);
    l0 += __shfl_xor_sync(0xffffffffu, l0, 2);
    l1 += __shfl_xor_sync(0xffffffffu, l1, 1);
    l1 += __shfl_xor_sync(0xffffffffu, l1, 2);

    // ---- epilogue: stage 16x64 tile in warp-private smem (myB region is
    //      free: last stage_load was for c=7, consumed at top of c=7), then
    //      write coalesced 128B lines to g_AOh ----
    const int gg = b >> 4, h = b & 15;
    const float inv0 = __fdividef(1.f, l0);
    const float inv1 = __fdividef(1.f, l1);
    __half* myO = (__half*)myB;          // 16 rows x 72-half stride (warp-private)
    #pragma unroll
    for (int j = 0; j < 8; j++) {
        int d = j*8 + 2*tg;
        *(unsigned*)&myO[g*72 + d]     = pack_h2(o[j][0]*inv0, o[j][1]*inv0);
        *(unsigned*)&myO[(g+8)*72 + d] = pack_h2(o[j][2]*inv1, o[j][3]*inv1);
    }
    __syncwarp();
    #pragma unroll
    for (int p = 0; p < 4; p++) {
        int row = p*4 + (lane >> 3);     // 0..15 within warp tile
        int ch  = lane & 7;              // 8 x 16B chunks per 128B row
        int n   = rb*64 + wid*16 + row;
        uint4 v = *(uint4*)&myO[row*72 + ch*8];
        *(uint4*)&g_AOh[(size_t)(n*NGRAPH + gg)*E_DIM + h*HD + ch*8] = v;
    }
}

// ---------------------------------------------------------------------------
// Mega-kernel (R10/R14 structure — measured best):
//   [0,768):    QKV tiles, bm fastest, grp-major columns
//   [768,1792): attention, gp-major (readiness order); waits g_cnt_qkv
//   [1792,2048): out-proj; waits g_cnt_attn
// ---------------------------------------------------------------------------
#define MEGA_SMEM ATTN_SMEM   // 82944 >= HGEMM_SMEM

__global__ __launch_bounds__(128, 2)
void mega_kernel(const float* __restrict__ in_b,
                 const float* __restrict__ attnbias,
                 const float* __restrict__ gaw,
                 const float* __restrict__ out_b,
                 float* __restrict__ out)
{
    extern __shared__ char smem[];
    const int cta = blockIdx.x;
    const int tid = threadIdx.x;

    if (cta < 768) {
        int bm  = cta & 31;
        int bnp = cta >> 5;                    // 0..23, grp-major
        int grp = bnp / 3, rem = bnp % 3;
        int L   = rem * 8 + grp;
        gemm_body<true>(smem, bm*128, L*128, in_b, nullptr);
        __threadfence();
        __syncthreads();
        if (tid == 0) atomicAdd(&g_cnt_qkv[grp], 1);
    } else if (cta < 1792) {
        int t  = cta - 768;
        int gp = t >> 7;                       // 0..7  (gp-major: best)
        int u  = t & 127;
        int rb = u >> 4;                       // 0..7
        int v  = u & 15;
        int gg = v >> 1, hh = v & 1;
        int b  = gg*NHEADS + gp*2 + hh;
        if (tid == 0) {
            while (atomicAdd(&g_cnt_qkv[gp], 0) < 96) __nanosleep(256);
        }
        __syncthreads();
        __threadfence();
        attn_body((__half*)smem, b, rb, attnbias, gaw);
        __threadfence();
        __syncthreads();
        if (tid == 0) atomicAdd(&g_cnt_attn[rb], 1);
    } else {
        int t  = cta - 1792;
        int bm = t & 31;
        int bn = t >> 5;
        if (tid == 0) {
            while (atomicAdd(&g_cnt_attn[bm >> 2], 0) < 128) __nanosleep(256);
        }
        __syncthreads();
        __threadfence();
        gemm_body<false>(smem, bm*128, bn*128, out_b, out);
    }
}

// ---------------------------------------------------------------------------
extern "C" void kernel_launch(void* const* d_in, const int* in_sizes, int n_in,
                              void* d_out, int out_size)
{
    const float* query    = (const float*)d_in[0];
    const float* attnbias = (const float*)d_in[1];
    const float* gaw      = (const float*)d_in[2];
    const float* in_w     = (const float*)d_in[3];
    const float* in_b     = (const float*)d_in[4];
    const float* out_w    = (const float*)d_in[5];
    const float* out_b    = (const float*)d_in[6];
    float* out = (float*)d_out;

    static int configured = 0;
    if (!configured) {
        cudaFuncSetAttribute(mega_kernel,
                             cudaFuncAttributeMaxDynamicSharedMemorySize, MEGA_SMEM);
        configured = 1;
    }

    cvt_kernel<<<CVT_GRID, 256>>>((const float4*)query, (const float4*)in_w,
                                  (const float4*)out_w);

    mega_kernel<<<2048, 128, MEGA_SMEM>>>(in_b, attnbias, gaw, out_b, out);
}